// round 13
// baseline (speedup 1.0000x reference)
#include <cuda_runtime.h>
#include <cuda_bf16.h>
#include <cstdint>
#include <cstddef>

// Problem constants
#define BB   8
#define TT   16
#define NN   196
#define CC   768
#define HH   12
#define HD   64
#define MROWS (BB*TT*NN)      // 25088
#define C3   (3*CC)           // 2304 (qkv width)
#define K3   (3*CC)           // 2304 (tripled-K for bf16 split emulation)

// ---------------------------------------------------------------------------
// Scratch: device globals (no allocation allowed)
// ---------------------------------------------------------------------------
__device__ float g_qkv[(size_t)MROWS * C3];            // [M, 3C] fp32
__device__ float g_xavg[(size_t)MROWS * CC];           // [M, C]  fp32 (x1)
__device__ float g_x2[(size_t)MROWS * CC];             // [M, C]  fp32 (x2)
__device__ __nv_bfloat16 g_x3[(size_t)MROWS * K3];     // [M, 3K] = [hi|hi|lo]
__device__ __nv_bfloat16 g_xavg3[(size_t)MROWS * K3];  // [M, 3K]
__device__ __nv_bfloat16 g_wqkv3[(size_t)C3 * K3];     // [N, 3K] = [hi|lo|hi] (W^T)
__device__ __nv_bfloat16 g_wproj3[(size_t)CC * K3];    // [N, 3K]

// ---------------------------------------------------------------------------
// Helpers
// ---------------------------------------------------------------------------
__device__ __forceinline__ uint32_t smem_u32(const void* p) {
    uint32_t a;
    asm("{ .reg .u64 t; cvta.to.shared.u64 t, %1; cvt.u32.u64 %0, t; }" : "=r"(a) : "l"(p));
    return a;
}
#define SWZ(o) ((o) ^ (((o) >> 3) & 0x70))

__device__ __forceinline__ void cp16(uint32_t d, const void* g) {
    asm volatile("cp.async.cg.shared.global [%0], [%1], 16;" :: "r"(d), "l"(g));
}
__device__ __forceinline__ void ldm_x4(uint32_t* r, uint32_t a) {
    asm volatile("ldmatrix.sync.aligned.m8n8.x4.shared.b16 {%0,%1,%2,%3}, [%4];"
                 : "=r"(r[0]), "=r"(r[1]), "=r"(r[2]), "=r"(r[3]) : "r"(a));
}
__device__ __forceinline__ void mma16816(float* c, const uint32_t* a, const uint32_t* b) {
    asm volatile(
        "mma.sync.aligned.m16n8k16.row.col.f32.bf16.bf16.f32 "
        "{%0,%1,%2,%3}, {%4,%5,%6,%7}, {%8,%9}, {%0,%1,%2,%3};"
        : "+f"(c[0]), "+f"(c[1]), "+f"(c[2]), "+f"(c[3])
        : "r"(a[0]), "r"(a[1]), "r"(a[2]), "r"(a[3]), "r"(b[0]), "r"(b[1]));
}

// ---------------------------------------------------------------------------
// Fused operand prep (one launch).
// ---------------------------------------------------------------------------
#define NBX  (MROWS * CC / 4 / 256)     // 18816
#define NBWQ (C3 * CC / 256)            // 6912
#define NBWP (CC * CC / 256)            // 2304

__device__ __forceinline__ void split3_store(
    __nv_bfloat16* __restrict__ out, size_t row, int c, int K,
    float x, float y, float z, float w)
{
    __nv_bfloat16 h0 = __float2bfloat16(x), h1 = __float2bfloat16(y);
    __nv_bfloat16 h2 = __float2bfloat16(z), h3 = __float2bfloat16(w);
    __nv_bfloat16 l0 = __float2bfloat16(x - __bfloat162float(h0));
    __nv_bfloat16 l1 = __float2bfloat16(y - __bfloat162float(h1));
    __nv_bfloat16 l2 = __float2bfloat16(z - __bfloat162float(h2));
    __nv_bfloat16 l3 = __float2bfloat16(w - __bfloat162float(h3));
    __nv_bfloat162 H01; H01.x = h0; H01.y = h1;
    __nv_bfloat162 H23; H23.x = h2; H23.y = h3;
    __nv_bfloat162 L01; L01.x = l0; L01.y = l1;
    __nv_bfloat162 L23; L23.x = l2; L23.y = l3;
    size_t b = row * 3 * K;
    __nv_bfloat162* o0 = (__nv_bfloat162*)(out + b) + c * 2;
    __nv_bfloat162* o1 = (__nv_bfloat162*)(out + b + K) + c * 2;
    __nv_bfloat162* o2 = (__nv_bfloat162*)(out + b + 2 * K) + c * 2;
    o0[0] = H01; o0[1] = H23;
    o1[0] = H01; o1[1] = H23;
    o2[0] = L01; o2[1] = L23;
}

__device__ __forceinline__ void split3_body(
    const float* __restrict__ in, __nv_bfloat16* __restrict__ out, int K, int i)
{
    const int K4 = K >> 2;
    const int row = i / K4, c = i % K4;
    float4 v = ((const float4*)in)[i];
    split3_store(out, row, c, K, v.x, v.y, v.z, v.w);
}

__device__ __forceinline__ void tsplit_body(
    const float* __restrict__ W, __nv_bfloat16* __restrict__ out, int K, int N, int i)
{
    const int k = i % K, n = i / K;
    float v = W[(size_t)k * N + n];
    __nv_bfloat16 h = __float2bfloat16(v);
    __nv_bfloat16 l = __float2bfloat16(v - __bfloat162float(h));
    size_t b = (size_t)n * 3 * K;
    out[b + k] = h;
    out[b + K + k] = l;
    out[b + 2 * K + k] = h;
}

__global__ void prep_all(const float* __restrict__ x,
                         const float* __restrict__ Wq,
                         const float* __restrict__ Wp,
                         __nv_bfloat16* __restrict__ x3,
                         __nv_bfloat16* __restrict__ wq3,
                         __nv_bfloat16* __restrict__ wp3)
{
    const int bid = blockIdx.x;
    if (bid < NBX) {
        split3_body(x, x3, CC, bid * 256 + threadIdx.x);
    } else if (bid < NBX + NBWQ) {
        tsplit_body(Wq, wq3, CC, C3, (bid - NBX) * 256 + threadIdx.x);
    } else {
        tsplit_body(Wp, wp3, CC, CC, (bid - NBX - NBWQ) * 256 + threadIdx.x);
    }
}

// ---------------------------------------------------------------------------
// avg + split: xavg3 = split3((x1 + x2) * 0.5)
// ---------------------------------------------------------------------------
__global__ void avgsplit(const float* __restrict__ a, const float* __restrict__ b,
                         __nv_bfloat16* __restrict__ out)
{
    const int i = blockIdx.x * 256 + threadIdx.x;
    const int K4 = CC >> 2;
    const int row = i / K4, c = i % K4;
    float4 va = ((const float4*)a)[i];
    float4 vb = ((const float4*)b)[i];
    split3_store(out, row, c, CC,
                 (va.x + vb.x) * 0.5f, (va.y + vb.y) * 0.5f,
                 (va.z + vb.z) * 0.5f, (va.w + vb.w) * 0.5f);
}

// ---------------------------------------------------------------------------
// mma.sync bf16 GEMM: 128x128 tile, BK=64, 3-stage cp.async (96KB, 2 CTA/SM).
// ---------------------------------------------------------------------------
template<bool BIAS>
__global__ void __launch_bounds__(256, 2) gemm_mma(
    const __nv_bfloat16* __restrict__ A,
    const __nv_bfloat16* __restrict__ Bm,
    const float* __restrict__ bias,
    float* __restrict__ Cm,
    int Kdim, int Ntot)
{
    extern __shared__ char smem[];
    const uint32_t sb = smem_u32(smem);
    const int tid = threadIdx.x, wid = tid >> 5, lane = tid & 31;
    const int m0 = blockIdx.y * 128, n0 = blockIdx.x * 128;
    const int wm = (wid >> 2) * 64;
    const int wn = (wid & 3) * 32;

    const __nv_bfloat16* Ag = A + (size_t)m0 * Kdim;
    const __nv_bfloat16* Bg = Bm + (size_t)n0 * Kdim;

    auto load_tile = [&](int k0, int buf) {
        uint32_t sa = sb + buf * 32768;
        uint32_t sB = sa + 16384;
#pragma unroll
        for (int i = 0; i < 4; i++) {
            int idx = tid + i * 256;
            int row = idx >> 3, c = idx & 7;
            size_t goff = (size_t)row * Kdim + k0 + c * 8;
            uint32_t soff = SWZ(row * 128 + c * 16);
            cp16(sa + soff, Ag + goff);
            cp16(sB + soff, Bg + goff);
        }
        asm volatile("cp.async.commit_group;" ::: "memory");
    };

    float acc[4][4][4];
#pragma unroll
    for (int i = 0; i < 4; i++)
#pragma unroll
        for (int j = 0; j < 4; j++)
#pragma unroll
            for (int k = 0; k < 4; k++) acc[i][j][k] = 0.f;

    const int nk = Kdim >> 6;
    load_tile(0, 0);
    load_tile(64, 1);

    int buf = 0;
    for (int it = 0; it < nk; ++it) {
        if (it + 2 < nk) {
            load_tile((it + 2) << 6, (it + 2) % 3);
            asm volatile("cp.async.wait_group 2;" ::: "memory");
        } else {
            asm volatile("cp.async.wait_group 0;" ::: "memory");
        }
        __syncthreads();

        uint32_t sa = sb + buf * 32768;
        uint32_t sB = sa + 16384;
#pragma unroll
        for (int ks = 0; ks < 4; ks++) {
            uint32_t afr[4][4], bfr[2][4];
#pragma unroll
            for (int mt = 0; mt < 4; mt++) {
                int row = wm + mt * 16 + (lane & 15);
                int kb = ks * 32 + ((lane >> 4) << 4);
                ldm_x4(afr[mt], sa + SWZ(row * 128 + kb));
            }
#pragma unroll
            for (int nt2 = 0; nt2 < 2; nt2++) {
                int row = wn + nt2 * 16 + ((lane >> 4) << 3) + (lane & 7);
                int kb = ks * 32 + (((lane >> 3) & 1) << 4);
                ldm_x4(bfr[nt2], sB + SWZ(row * 128 + kb));
            }
#pragma unroll
            for (int mt = 0; mt < 4; mt++)
#pragma unroll
                for (int nt = 0; nt < 4; nt++)
                    mma16816(acc[mt][nt], afr[mt], &bfr[nt >> 1][(nt & 1) * 2]);
        }
        __syncthreads();
        buf = (buf + 1 == 3) ? 0 : buf + 1;
    }

#pragma unroll
    for (int mt = 0; mt < 4; mt++) {
        int r0 = m0 + wm + mt * 16 + (lane >> 2);
#pragma unroll
        for (int nt = 0; nt < 4; nt++) {
            int col = n0 + wn + nt * 8 + (lane & 3) * 2;
            float2 v0, v1;
            v0.x = acc[mt][nt][0]; v0.y = acc[mt][nt][1];
            v1.x = acc[mt][nt][2]; v1.y = acc[mt][nt][3];
            if (BIAS) {
                float b0 = bias[col], b1 = bias[col + 1];
                v0.x += b0; v0.y += b1;
                v1.x += b0; v1.y += b1;
            }
            *(float2*)(Cm + (size_t)r0 * Ntot + col) = v0;
            *(float2*)(Cm + (size_t)(r0 + 8) * Ntot + col) = v1;
        }
    }
}

// ---------------------------------------------------------------------------
// Spatial attention v3 (unchanged): writes x1 -> g_xavg.
// ---------------------------------------------------------------------------
#define KSTR 68
__global__ void __launch_bounds__(256) spatial_attn(
    const float* __restrict__ qkv, float* __restrict__ xavg)
{
    extern __shared__ float sm[];
    float* Ks  = sm;
    float* VsT = Ks + 196 * KSTR;
    float* sPQ = VsT + 64 * 196;

    const int bid = blockIdx.x;
    const int h   = bid % HH;
    const int bt  = bid / HH;
    const float* base = qkv + (size_t)bt * NN * C3 + h * HD;

    for (int idx = threadIdx.x; idx < NN * HD; idx += 256) {
        int m = idx >> 6, d = idx & 63;
        size_t g = (size_t)m * C3 + d;
        Ks[m * KSTR + d]  = base[g + CC];
        VsT[d * 196 + m]  = base[g + 2 * CC];
    }
    __syncthreads();

    const int w = threadIdx.x >> 5;
    const int lane = threadIdx.x & 31;
    float* myPQ = sPQ + w * 392;

    for (int p = w; p < 98; p += 8) {
        const int r0 = 2 * p;

        const float* q0p = base + (size_t)r0 * C3;
        myPQ[lane]       = q0p[lane];
        myPQ[lane + 32]  = q0p[lane + 32];
        myPQ[64 + lane]  = q0p[C3 + lane];
        myPQ[96 + lane]  = q0p[C3 + lane + 32];
        __syncwarp();

        float sc0[7], sc1[7];
#pragma unroll
        for (int j = 0; j < 7; j++) { sc0[j] = 0.f; sc1[j] = 0.f; }

#pragma unroll 4
        for (int dq = 0; dq < 16; dq++) {
            float4 q0 = *(float4*)&myPQ[dq * 4];
            float4 q1 = *(float4*)&myPQ[64 + dq * 4];
#pragma unroll
            for (int j = 0; j < 7; j++) {
                float4 k4 = *(float4*)&Ks[(lane + 32 * j) * KSTR + dq * 4];
                sc0[j] += q0.x * k4.x + q0.y * k4.y + q0.z * k4.z + q0.w * k4.w;
                sc1[j] += q1.x * k4.x + q1.y * k4.y + q1.z * k4.z + q1.w * k4.w;
            }
        }
        __syncwarp();

        {
            float mx = -1e30f;
#pragma unroll
            for (int j = 0; j < 7; j++) {
                int m = lane + 32 * j;
                sc0[j] = (m < NN) ? sc0[j] * 0.125f : -1e30f;
                mx = fmaxf(mx, sc0[j]);
            }
#pragma unroll
            for (int o = 16; o; o >>= 1) mx = fmaxf(mx, __shfl_xor_sync(0xffffffffu, mx, o));
            float sum = 0.f;
#pragma unroll
            for (int j = 0; j < 7; j++) {
                int m = lane + 32 * j;
                float e = (m < NN) ? expf(sc0[j] - mx) : 0.f;
                sc0[j] = e; sum += e;
            }
#pragma unroll
            for (int o = 16; o; o >>= 1) sum += __shfl_xor_sync(0xffffffffu, sum, o);
            float inv = 1.f / sum;
#pragma unroll
            for (int j = 0; j < 7; j++) {
                int m = lane + 32 * j;
                if (m < NN) myPQ[m] = sc0[j] * inv;
            }
        }
        {
            float mx = -1e30f;
#pragma unroll
            for (int j = 0; j < 7; j++) {
                int m = lane + 32 * j;
                sc1[j] = (m < NN) ? sc1[j] * 0.125f : -1e30f;
                mx = fmaxf(mx, sc1[j]);
            }
#pragma unroll
            for (int o = 16; o; o >>= 1) mx = fmaxf(mx, __shfl_xor_sync(0xffffffffu, mx, o));
            float sum = 0.f;
#pragma unroll
            for (int j = 0; j < 7; j++) {
                int m = lane + 32 * j;
                float e = (m < NN) ? expf(sc1[j] - mx) : 0.f;
                sc1[j] = e; sum += e;
            }
#pragma unroll
            for (int o = 16; o; o >>= 1) sum += __shfl_xor_sync(0xffffffffu, sum, o);
            float inv = 1.f / sum;
#pragma unroll
            for (int j = 0; j < 7; j++) {
                int m = lane + 32 * j;
                if (m < NN) myPQ[196 + m] = sc1[j] * inv;
            }
        }
        __syncwarp();

        const float* v0row = VsT + (size_t)lane * 196;
        const float* v1row = VsT + (size_t)(lane + 32) * 196;
        float a00 = 0.f, a01 = 0.f, a10 = 0.f, a11 = 0.f;
#pragma unroll 7
        for (int m = 0; m < 196; m += 4) {
            float4 p0 = *(float4*)&myPQ[m];
            float4 p1 = *(float4*)&myPQ[196 + m];
            float4 v0 = *(const float4*)&v0row[m];
            float4 v1 = *(const float4*)&v1row[m];
            a00 += p0.x * v0.x + p0.y * v0.y + p0.z * v0.z + p0.w * v0.w;
            a01 += p0.x * v1.x + p0.y * v1.y + p0.z * v1.z + p0.w * v1.w;
            a10 += p1.x * v0.x + p1.y * v0.y + p1.z * v0.z + p1.w * v0.w;
            a11 += p1.x * v1.x + p1.y * v1.y + p1.z * v1.z + p1.w * v1.w;
        }
        size_t o0 = ((size_t)bt * NN + r0) * CC + h * HD;
        xavg[o0 + lane]           = a00;
        xavg[o0 + 32 + lane]      = a01;
        xavg[o0 + CC + lane]      = a10;
        xavg[o0 + CC + 32 + lane] = a11;
        __syncwarp();
    }
}

// ---------------------------------------------------------------------------
// Temporal attention: writes x2 (fp32, coalesced plain stores).
// ---------------------------------------------------------------------------
__global__ void temporal_attn(const float* __restrict__ qkv,
                              float* __restrict__ x2)
{
    extern __shared__ float sm[];
    const int w = threadIdx.x >> 5;
    const int lane = threadIdx.x & 31;
    float* qs = sm + (size_t)w * 3 * 16 * 65;
    float* ks = qs + 16 * 65;
    float* vs = ks + 16 * 65;

    const int inst = blockIdx.x * 4 + w;
    const int n  = inst % NN;
    const int bh = inst / NN;
    const int h  = bh % HH;
    const int b  = bh / HH;

    const size_t tstride = (size_t)NN * C3;
    const float* base = qkv + ((size_t)(b * TT) * NN + n) * C3 + h * HD;

    for (int idx = lane; idx < TT * HD; idx += 32) {
        int t = idx >> 6, d = idx & 63;
        size_t g = (size_t)t * tstride + d;
        qs[t * 65 + d] = base[g];
        ks[t * 65 + d] = base[g + CC];
        vs[t * 65 + d] = base[g + 2 * CC];
    }
    __syncwarp();

    float p[TT];
    if (lane < TT) {
        const int t = lane;
        float mx = -1e30f;
#pragma unroll
        for (int s = 0; s < TT; s++) {
            float acc = 0.f;
#pragma unroll 8
            for (int d = 0; d < HD; d++) acc += qs[t * 65 + d] * ks[s * 65 + d];
            acc *= 0.125f;
            p[s] = acc;
            mx = fmaxf(mx, acc);
        }
        float sum = 0.f;
#pragma unroll
        for (int s = 0; s < TT; s++) { p[s] = expf(p[s] - mx); sum += p[s]; }
        float inv = 1.f / sum;
#pragma unroll
        for (int s = 0; s < TT; s++) p[s] *= inv;
    }
    __syncwarp();

    if (lane < TT) {
        const int t = lane;
        for (int d = 0; d < HD; d++) {
            float acc = 0.f;
#pragma unroll
            for (int s = 0; s < TT; s++) acc += p[s] * vs[s * 65 + d];
            qs[t * 65 + d] = acc;
        }
    }
    __syncwarp();

    const size_t obase = ((size_t)(b * TT) * NN + n) * CC + h * HD;
    const size_t ostride = (size_t)NN * CC;
    for (int t = 0; t < TT; t++) {
        size_t o = obase + (size_t)t * ostride;
        x2[o + lane]      = qs[t * 65 + lane];
        x2[o + 32 + lane] = qs[t * 65 + 32 + lane];
    }
}

// ---------------------------------------------------------------------------
extern "C" void kernel_launch(void* const* d_in, const int* in_sizes, int n_in,
                              void* d_out, int out_size)
{
    const float* x      = (const float*)d_in[0];
    const float* W_qkv  = (const float*)d_in[1];
    const float* W_proj = (const float*)d_in[2];
    const float* b_proj = (const float*)d_in[3];
    float* out = (float*)d_out;

    float* qkv;   cudaGetSymbolAddress((void**)&qkv,   g_qkv);
    float* xavg;  cudaGetSymbolAddress((void**)&xavg,  g_xavg);
    float* x2;    cudaGetSymbolAddress((void**)&x2,    g_x2);
    __nv_bfloat16* x3;     cudaGetSymbolAddress((void**)&x3,     g_x3);
    __nv_bfloat16* xavg3;  cudaGetSymbolAddress((void**)&xavg3,  g_xavg3);
    __nv_bfloat16* wqkv3;  cudaGetSymbolAddress((void**)&wqkv3,  g_wqkv3);
    __nv_bfloat16* wproj3; cudaGetSymbolAddress((void**)&wproj3, g_wproj3);

    const int gemm_smem = 98304;                                   // 3 x 32KB
    const int spat_smem = (196 * KSTR + 64 * 196 + 8 * 392) * 4;   // 116,032 B
    const int temp_smem = 4 * 3 * 16 * 65 * 4;                     // 49,920 B

    static cudaStream_t s2 = nullptr;
    static cudaEvent_t ev_fork = nullptr, ev_join = nullptr;
    static bool init_done = false;
    if (!init_done) {
        cudaFuncSetAttribute(gemm_mma<false>, cudaFuncAttributeMaxDynamicSharedMemorySize, gemm_smem);
        cudaFuncSetAttribute(gemm_mma<true>,  cudaFuncAttributeMaxDynamicSharedMemorySize, gemm_smem);
        cudaFuncSetAttribute(spatial_attn,    cudaFuncAttributeMaxDynamicSharedMemorySize, spat_smem);
        cudaFuncSetAttribute(temporal_attn,   cudaFuncAttributeMaxDynamicSharedMemorySize, temp_smem);
        cudaStreamCreateWithFlags(&s2, cudaStreamNonBlocking);
        cudaEventCreateWithFlags(&ev_fork, cudaEventDisableTiming);
        cudaEventCreateWithFlags(&ev_join, cudaEventDisableTiming);
        init_done = true;
    }

    // 0) fused operand prep
    prep_all<<<NBX + NBWQ + NBWP, 256>>>(x, W_qkv, W_proj, x3, wqkv3, wproj3);

    // 1) qkv = x @ W_qkv
    gemm_mma<false><<<dim3(C3 / 128, MROWS / 128), 256, gemm_smem>>>(
        x3, wqkv3, nullptr, qkv, K3, C3);

    // 2) fork: temporal (stream s2) || spatial (main stream)
    cudaEventRecord(ev_fork, 0);
    cudaStreamWaitEvent(s2, ev_fork, 0);
    temporal_attn<<<(BB * HH * NN) / 4, 128, temp_smem, s2>>>(qkv, x2);
    spatial_attn<<<BB * TT * HH, 256, spat_smem>>>(qkv, xavg);
    cudaEventRecord(ev_join, s2);
    cudaStreamWaitEvent(0, ev_join, 0);

    // 3) xavg3 = split3((x1 + x2) * 0.5)
    avgsplit<<<NBX, 256>>>(xavg, x2, xavg3);

    // 4) out = xavg @ W_proj + b_proj
    gemm_mma<true><<<dim3(CC / 128, MROWS / 128), 256, gemm_smem>>>(
        xavg3, wproj3, b_proj, out, K3, CC);
}

// round 16
// speedup vs baseline: 1.1072x; 1.1072x over previous
#include <cuda_runtime.h>
#include <cuda_bf16.h>
#include <cstdint>
#include <cstddef>

// Problem constants
#define BB   8
#define TT   16
#define NN   196
#define CC   768
#define HH   12
#define HD   64
#define MROWS (BB*TT*NN)      // 25088
#define C3   (3*CC)           // 2304 (qkv width)
#define K3   (3*CC)           // 2304 (tripled-K for bf16 split emulation)

// ---------------------------------------------------------------------------
// Scratch: device globals (no allocation allowed)
// ---------------------------------------------------------------------------
__device__ float g_qkv[(size_t)MROWS * C3];            // [M, 3C] fp32
__device__ float g_xavg[(size_t)MROWS * CC];           // [M, C]  fp32 (x1)
__device__ __nv_bfloat16 g_x3[(size_t)MROWS * K3];     // [M, 3K] = [hi|hi|lo]
__device__ __nv_bfloat16 g_xavg3[(size_t)MROWS * K3];  // [M, 3K]
__device__ __nv_bfloat16 g_wqkv3[(size_t)C3 * K3];     // [N, 3K] = [hi|lo|hi] (W^T)
__device__ __nv_bfloat16 g_wproj3[(size_t)CC * K3];    // [N, 3K]

// ---------------------------------------------------------------------------
// Helpers
// ---------------------------------------------------------------------------
__device__ __forceinline__ uint32_t smem_u32(const void* p) {
    uint32_t a;
    asm("{ .reg .u64 t; cvta.to.shared.u64 t, %1; cvt.u32.u64 %0, t; }" : "=r"(a) : "l"(p));
    return a;
}
#define SWZ(o) ((o) ^ (((o) >> 3) & 0x70))

__device__ __forceinline__ void cp16(uint32_t d, const void* g) {
    asm volatile("cp.async.cg.shared.global [%0], [%1], 16;" :: "r"(d), "l"(g));
}
__device__ __forceinline__ void ldm_x4(uint32_t* r, uint32_t a) {
    asm volatile("ldmatrix.sync.aligned.m8n8.x4.shared.b16 {%0,%1,%2,%3}, [%4];"
                 : "=r"(r[0]), "=r"(r[1]), "=r"(r[2]), "=r"(r[3]) : "r"(a));
}
__device__ __forceinline__ void mma16816(float* c, const uint32_t* a, const uint32_t* b) {
    asm volatile(
        "mma.sync.aligned.m16n8k16.row.col.f32.bf16.bf16.f32 "
        "{%0,%1,%2,%3}, {%4,%5,%6,%7}, {%8,%9}, {%0,%1,%2,%3};"
        : "+f"(c[0]), "+f"(c[1]), "+f"(c[2]), "+f"(c[3])
        : "r"(a[0]), "r"(a[1]), "r"(a[2]), "r"(a[3]), "r"(b[0]), "r"(b[1]));
}

// ---------------------------------------------------------------------------
// Fused operand prep (one launch).
// ---------------------------------------------------------------------------
#define NBX  (MROWS * CC / 4 / 256)     // 18816
#define NBWQ (C3 * CC / 256)            // 6912
#define NBWP (CC * CC / 256)            // 2304

__device__ __forceinline__ void split3_body(
    const float* __restrict__ in, __nv_bfloat16* __restrict__ out, int K, int i)
{
    const int K4 = K >> 2;
    const int row = i / K4, c = i % K4;
    float4 v = ((const float4*)in)[i];
    __nv_bfloat16 h0 = __float2bfloat16(v.x), h1 = __float2bfloat16(v.y);
    __nv_bfloat16 h2 = __float2bfloat16(v.z), h3 = __float2bfloat16(v.w);
    __nv_bfloat16 l0 = __float2bfloat16(v.x - __bfloat162float(h0));
    __nv_bfloat16 l1 = __float2bfloat16(v.y - __bfloat162float(h1));
    __nv_bfloat16 l2 = __float2bfloat16(v.z - __bfloat162float(h2));
    __nv_bfloat16 l3 = __float2bfloat16(v.w - __bfloat16\
2float(h3));
    __nv_bfloat162 H01; H01.x = h0; H01.y = h1;
    __nv_bfloat162 H23; H23.x = h2; H23.y = h3;
    __nv_bfloat162 L01; L01.x = l0; L01.y = l1;
    __nv_bfloat162 L23; L23.x = l2; L23.y = l3;
    size_t b = (size_t)row * 3 * K;
    __nv_bfloat162* o0 = (__nv_bfloat162*)(out + b) + c * 2;
    __nv_bfloat162* o1 = (__nv_bfloat162*)(out + b + K) + c * 2;
    __nv_bfloat162* o2 = (__nv_bfloat162*)(out + b + 2 * K) + c * 2;
    o0[0] = H01; o0[1] = H23;
    o1[0] = H01; o1[1] = H23;
    o2[0] = L01; o2[1] = L23;
}

__device__ __forceinline__ void tsplit_body(
    const float* __restrict__ W, __nv_bfloat16* __restrict__ out, int K, int N, int i)
{
    const int k = i % K, n = i / K;
    float v = W[(size_t)k * N + n];
    __nv_bfloat16 h = __float2bfloat16(v);
    __nv_bfloat16 l = __float2bfloat16(v - __bfloat162float(h));
    size_t b = (size_t)n * 3 * K;
    out[b + k] = h;
    out[b + K + k] = l;
    out[b + 2 * K + k] = h;
}

__global__ void prep_all(const float* __restrict__ x,
                         const float* __restrict__ Wq,
                         const float* __restrict__ Wp,
                         __nv_bfloat16* __restrict__ x3,
                         __nv_bfloat16* __restrict__ wq3,
                         __nv_bfloat16* __restrict__ wp3)
{
    const int bid = blockIdx.x;
    if (bid < NBX) {
        split3_body(x, x3, CC, bid * 256 + threadIdx.x);
    } else if (bid < NBX + NBWQ) {
        tsplit_body(Wq, wq3, CC, C3, (bid - NBX) * 256 + threadIdx.x);
    } else {
        tsplit_body(Wp, wp3, CC, CC, (bid - NBX - NBWQ) * 256 + threadIdx.x);
    }
}

// ---------------------------------------------------------------------------
// mma.sync bf16 GEMM: 128x128 tile, BK=64, 3-stage cp.async (96KB, 2 CTA/SM).
// ---------------------------------------------------------------------------
template<bool BIAS>
__global__ void __launch_bounds__(256, 2) gemm_mma(
    const __nv_bfloat16* __restrict__ A,
    const __nv_bfloat16* __restrict__ Bm,
    const float* __restrict__ bias,
    float* __restrict__ Cm,
    int Kdim, int Ntot)
{
    extern __shared__ char smem[];
    const uint32_t sb = smem_u32(smem);
    const int tid = threadIdx.x, wid = tid >> 5, lane = tid & 31;
    const int m0 = blockIdx.y * 128, n0 = blockIdx.x * 128;
    const int wm = (wid >> 2) * 64;
    const int wn = (wid & 3) * 32;

    const __nv_bfloat16* Ag = A + (size_t)m0 * Kdim;
    const __nv_bfloat16* Bg = Bm + (size_t)n0 * Kdim;

    auto load_tile = [&](int k0, int buf) {
        uint32_t sa = sb + buf * 32768;
        uint32_t sB = sa + 16384;
#pragma unroll
        for (int i = 0; i < 4; i++) {
            int idx = tid + i * 256;
            int row = idx >> 3, c = idx & 7;
            size_t goff = (size_t)row * Kdim + k0 + c * 8;
            uint32_t soff = SWZ(row * 128 + c * 16);
            cp16(sa + soff, Ag + goff);
            cp16(sB + soff, Bg + goff);
        }
        asm volatile("cp.async.commit_group;" ::: "memory");
    };

    float acc[4][4][4];
#pragma unroll
    for (int i = 0; i < 4; i++)
#pragma unroll
        for (int j = 0; j < 4; j++)
#pragma unroll
            for (int k = 0; k < 4; k++) acc[i][j][k] = 0.f;

    const int nk = Kdim >> 6;
    load_tile(0, 0);
    load_tile(64, 1);

    int buf = 0;
    for (int it = 0; it < nk; ++it) {
        if (it + 2 < nk) {
            load_tile((it + 2) << 6, (it + 2) % 3);
            asm volatile("cp.async.wait_group 2;" ::: "memory");
        } else {
            asm volatile("cp.async.wait_group 0;" ::: "memory");
        }
        __syncthreads();

        uint32_t sa = sb + buf * 32768;
        uint32_t sB = sa + 16384;
#pragma unroll
        for (int ks = 0; ks < 4; ks++) {
            uint32_t afr[4][4], bfr[2][4];
#pragma unroll
            for (int mt = 0; mt < 4; mt++) {
                int row = wm + mt * 16 + (lane & 15);
                int kb = ks * 32 + ((lane >> 4) << 4);
                ldm_x4(afr[mt], sa + SWZ(row * 128 + kb));
            }
#pragma unroll
            for (int nt2 = 0; nt2 < 2; nt2++) {
                int row = wn + nt2 * 16 + ((lane >> 4) << 3) + (lane & 7);
                int kb = ks * 32 + (((lane >> 3) & 1) << 4);
                ldm_x4(bfr[nt2], sB + SWZ(row * 128 + kb));
            }
#pragma unroll
            for (int mt = 0; mt < 4; mt++)
#pragma unroll
                for (int nt = 0; nt < 4; nt++)
                    mma16816(acc[mt][nt], afr[mt], &bfr[nt >> 1][(nt & 1) * 2]);
        }
        __syncthreads();
        buf = (buf + 1 == 3) ? 0 : buf + 1;
    }

#pragma unroll
    for (int mt = 0; mt < 4; mt++) {
        int r0 = m0 + wm + mt * 16 + (lane >> 2);
#pragma unroll
        for (int nt = 0; nt < 4; nt++) {
            int col = n0 + wn + nt * 8 + (lane & 3) * 2;
            float2 v0, v1;
            v0.x = acc[mt][nt][0]; v0.y = acc[mt][nt][1];
            v1.x = acc[mt][nt][2]; v1.y = acc[mt][nt][3];
            if (BIAS) {
                float b0 = bias[col], b1 = bias[col + 1];
                v0.x += b0; v0.y += b1;
                v1.x += b0; v1.y += b1;
            }
            *(float2*)(Cm + (size_t)r0 * Ntot + col) = v0;
            *(float2*)(Cm + (size_t)(r0 + 8) * Ntot + col) = v1;
        }
    }
}

// ---------------------------------------------------------------------------
// Spatial attention v4: one CTA per (b,t,h). 2 query rows per warp.
// Ks stride-64 with chunk-XOR swizzle (c' = c ^ (row&15)) — conflict-free
// float4 loads at 50,176 B. VsT transposed [64][196]. Warp-private q/P alias.
// Total smem = 112,896 B -> 2 CTAs/SM.
// ---------------------------------------------------------------------------
#define KIDX(row, d) ((row) * 64 + (((((d) >> 2) ^ ((row) & 15)) << 2) | ((d) & 3)))

__global__ void __launch_bounds__(256, 2) spatial_attn(
    const float* __restrict__ qkv, float* __restrict__ xavg)
{
    extern __shared__ float sm[];
    float* Ks  = sm;                        // 196*64 = 12544 floats (swizzled)
    float* VsT = Ks + 196 * 64;             // 64*196 = 12544 floats
    float* sPQ = VsT + 64 * 196;            // 8 warps * 392 floats

    const int bid = blockIdx.x;
    const int h   = bid % HH;
    const int bt  = bid / HH;
    const float* base = qkv + (size_t)bt * NN * C3 + h * HD;

    for (int idx = threadIdx.x; idx < NN * HD; idx += 256) {
        int m = idx >> 6, d = idx & 63;
        size_t g = (size_t)m * C3 + d;
        Ks[KIDX(m, d)]   = base[g + CC];
        VsT[d * 196 + m] = base[g + 2 * CC];
    }
    __syncthreads();

    const int w = threadIdx.x >> 5;
    const int lane = threadIdx.x & 31;
    float* myPQ = sPQ + w * 392;
    const int lsw = lane & 15;              // row&15 == lane&15 for row=lane+32j

    for (int p = w; p < 98; p += 8) {
        const int r0 = 2 * p;

        const float* q0p = base + (size_t)r0 * C3;
        myPQ[lane]       = q0p[lane];
        myPQ[lane + 32]  = q0p[lane + 32];
        myPQ[64 + lane]  = q0p[C3 + lane];
        myPQ[96 + lane]  = q0p[C3 + lane + 32];
        __syncwarp();

        float sc0[7], sc1[7];
#pragma unroll
        for (int j = 0; j < 7; j++) { sc0[j] = 0.f; sc1[j] = 0.f; }

#pragma unroll 4
        for (int dq = 0; dq < 16; dq++) {
            float4 q0 = *(float4*)&myPQ[dq * 4];
            float4 q1 = *(float4*)&myPQ[64 + dq * 4];
            const int co = (dq ^ lsw) << 2;
#pragma unroll
            for (int j = 0; j < 7; j++) {
                float4 k4 = *(float4*)&Ks[(lane + 32 * j) * 64 + co];
                sc0[j] += q0.x * k4.x + q0.y * k4.y + q0.z * k4.z + q0.w * k4.w;
                sc1[j] += q1.x * k4.x + q1.y * k4.y + q1.z * k4.z + q1.w * k4.w;
            }
        }
        __syncwarp();

        {
            float mx = -1e30f;
#pragma unroll
            for (int j = 0; j < 7; j++) {
                int m = lane + 32 * j;
                sc0[j] = (m < NN) ? sc0[j] * 0.125f : -1e30f;
                mx = fmaxf(mx, sc0[j]);
            }
#pragma unroll
            for (int o = 16; o; o >>= 1) mx = fmaxf(mx, __shfl_xor_sync(0xffffffffu, mx, o));
            float sum = 0.f;
#pragma unroll
            for (int j = 0; j < 7; j++) {
                int m = lane + 32 * j;
                float e = (m < NN) ? expf(sc0[j] - mx) : 0.f;
                sc0[j] = e; sum += e;
            }
#pragma unroll
            for (int o = 16; o; o >>= 1) sum += __shfl_xor_sync(0xffffffffu, sum, o);
            float inv = 1.f / sum;
#pragma unroll
            for (int j = 0; j < 7; j++) {
                int m = lane + 32 * j;
                if (m < NN) myPQ[m] = sc0[j] * inv;
            }
        }
        {
            float mx = -1e30f;
#pragma unroll
            for (int j = 0; j < 7; j++) {
                int m = lane + 32 * j;
                sc1[j] = (m < NN) ? sc1[j] * 0.125f : -1e30f;
                mx = fmaxf(mx, sc1[j]);
            }
#pragma unroll
            for (int o = 16; o; o >>= 1) mx = fmaxf(mx, __shfl_xor_sync(0xffffffffu, mx, o));
            float sum = 0.f;
#pragma unroll
            for (int j = 0; j < 7; j++) {
                int m = lane + 32 * j;
                float e = (m < NN) ? expf(sc1[j] - mx) : 0.f;
                sc1[j] = e; sum += e;
            }
#pragma unroll
            for (int o = 16; o; o >>= 1) sum += __shfl_xor_sync(0xffffffffu, sum, o);
            float inv = 1.f / sum;
#pragma unroll
            for (int j = 0; j < 7; j++) {
                int m = lane + 32 * j;
                if (m < NN) myPQ[196 + m] = sc1[j] * inv;
            }
        }
        __syncwarp();

        const float* v0row = VsT + (size_t)lane * 196;
        const float* v1row = VsT + (size_t)(lane + 32) * 196;
        float a00 = 0.f, a01 = 0.f, a10 = 0.f, a11 = 0.f;
#pragma unroll 7
        for (int m = 0; m < 196; m += 4) {
            float4 p0 = *(float4*)&myPQ[m];
            float4 p1 = *(float4*)&myPQ[196 + m];
            float4 v0 = *(const float4*)&v0row[m];
            float4 v1 = *(const float4*)&v1row[m];
            a00 += p0.x * v0.x + p0.y * v0.y + p0.z * v0.z + p0.w * v0.w;
            a01 += p0.x * v1.x + p0.y * v1.y + p0.z * v1.z + p0.w * v1.w;
            a10 += p1.x * v0.x + p1.y * v0.y + p1.z * v0.z + p1.w * v0.w;
            a11 += p1.x * v1.x + p1.y * v1.y + p1.z * v1.z + p1.w * v1.w;
        }
        size_t o0 = ((size_t)bt * NN + r0) * CC + h * HD;
        xavg[o0 + lane]           = a00;
        xavg[o0 + 32 + lane]      = a01;
        xavg[o0 + CC + lane]      = a10;
        xavg[o0 + CC + 32 + lane] = a11;
        __syncwarp();
    }
}

// ---------------------------------------------------------------------------
// Temporal attention: 4 warps/CTA, one (b,h,n) instance per warp.
// Finalizes (x1+x2)*0.5 and writes bf16 split [hi|hi|lo] into xavg3.
// ---------------------------------------------------------------------------
__global__ void temporal_attn(const float* __restrict__ qkv,
                              const float* __restrict__ xavg,
                              __nv_bfloat16* __restrict__ xavg3)
{
    extern __shared__ float sm[];
    const int w = threadIdx.x >> 5;
    const int lane = threadIdx.x & 31;
    float* qs = sm + (size_t)w * 3 * 16 * 65;
    float* ks = qs + 16 * 65;
    float* vs = ks + 16 * 65;

    const int inst = blockIdx.x * 4 + w;
    const int n  = inst % NN;
    const int bh = inst / NN;
    const int h  = bh % HH;
    const int b  = bh / HH;

    const size_t tstride = (size_t)NN * C3;
    const float* base = qkv + ((size_t)(b * TT) * NN + n) * C3 + h * HD;

    for (int idx = lane; idx < TT * HD; idx += 32) {
        int t = idx >> 6, d = idx & 63;
        size_t g = (size_t)t * tstride + d;
        qs[t * 65 + d] = base[g];
        ks[t * 65 + d] = base[g + CC];
        vs[t * 65 + d] = base[g + 2 * CC];
    }
    __syncwarp();

    float p[TT];
    if (lane < TT) {
        const int t = lane;
        float mx = -1e30f;
#pragma unroll
        for (int s = 0; s < TT; s++) {
            float acc = 0.f;
#pragma unroll 8
            for (int d = 0; d < HD; d++) acc += qs[t * 65 + d] * ks[s * 65 + d];
            acc *= 0.125f;
            p[s] = acc;
            mx = fmaxf(mx, acc);
        }
        float sum = 0.f;
#pragma unroll
        for (int s = 0; s < TT; s++) { p[s] = expf(p[s] - mx); sum += p[s]; }
        float inv = 1.f / sum;
#pragma unroll
        for (int s = 0; s < TT; s++) p[s] *= inv;
    }
    __syncwarp();

    if (lane < TT) {
        const int t = lane;
        for (int d = 0; d < HD; d++) {
            float acc = 0.f;
#pragma unroll
            for (int s = 0; s < TT; s++) acc += p[s] * vs[s * 65 + d];
            qs[t * 65 + d] = acc;
        }
    }
    __syncwarp();

    const size_t obase = ((size_t)(b * TT) * NN + n) * CC + h * HD;
    const size_t ostride = (size_t)NN * CC;
    const int col0 = h * HD + lane;
    for (int t = 0; t < TT; t++) {
        size_t o = obase + (size_t)t * ostride;
        float s0 = (xavg[o + lane]      + qs[t * 65 + lane])      * 0.5f;
        float s1 = (xavg[o + 32 + lane] + qs[t * 65 + 32 + lane]) * 0.5f;
        size_t row = (size_t)(b * TT + t) * NN + n;
        __nv_bfloat16* r3 = xavg3 + row * K3;
        __nv_bfloat16 h0 = __float2bfloat16(s0);
        __nv_bfloat16 h1 = __float2bfloat16(s1);
        __nv_bfloat16 l0 = __float2bfloat16(s0 - __bfloat162float(h0));
        __nv_bfloat16 l1 = __float2bfloat16(s1 - __bfloat162float(h1));
        r3[col0]                 = h0;  r3[col0 + 32]           = h1;
        r3[CC + col0]            = h0;  r3[CC + col0 + 32]      = h1;
        r3[2 * CC + col0]        = l0;  r3[2 * CC + col0 + 32]  = l1;
    }
}

// ---------------------------------------------------------------------------
extern "C" void kernel_launch(void* const* d_in, const int* in_sizes, int n_in,
                              void* d_out, int out_size)
{
    const float* x      = (const float*)d_in[0];
    const float* W_qkv  = (const float*)d_in[1];
    const float* W_proj = (const float*)d_in[2];
    const float* b_proj = (const float*)d_in[3];
    float* out = (float*)d_out;

    float* qkv;   cudaGetSymbolAddress((void**)&qkv,   g_qkv);
    float* xavg;  cudaGetSymbolAddress((void**)&xavg,  g_xavg);
    __nv_bfloat16* x3;     cudaGetSymbolAddress((void**)&x3,     g_x3);
    __nv_bfloat16* xavg3;  cudaGetSymbolAddress((void**)&xavg3,  g_xavg3);
    __nv_bfloat16* wqkv3;  cudaGetSymbolAddress((void**)&wqkv3,  g_wqkv3);
    __nv_bfloat16* wproj3; cudaGetSymbolAddress((void**)&wproj3, g_wproj3);

    const int gemm_smem = 98304;                                   // 3 x 32KB
    const int spat_smem = (196 * 64 + 64 * 196 + 8 * 392) * 4;     // 112,896 B
    const int temp_smem = 4 * 3 * 16 * 65 * 4;                     // 49,920 B
    static bool attr_done = false;
    if (!attr_done) {
        cudaFuncSetAttribute(gemm_mma<false>, cudaFuncAttributeMaxDynamicSharedMemorySize, gemm_smem);
        cudaFuncSetAttribute(gemm_mma<true>,  cudaFuncAttributeMaxDynamicSharedMemorySize, gemm_smem);
        cudaFuncSetAttribute(spatial_attn,    cudaFuncAttributeMaxDynamicSharedMemorySize, spat_smem);
        cudaFuncSetAttribute(temporal_attn,   cudaFuncAttributeMaxDynamicSharedMemorySize, temp_smem);
        attr_done = true;
    }

    // 0) fused operand prep
    prep_all<<<NBX + NBWQ + NBWP, 256>>>(x, W_qkv, W_proj, x3, wqkv3, wproj3);

    // 1) qkv = x @ W_qkv
    gemm_mma<false><<<dim3(C3 / 128, MROWS / 128), 256, gemm_smem>>>(
        x3, wqkv3, nullptr, qkv, K3, C3);

    // 2) spatial attention -> g_xavg (x1)
    spatial_attn<<<BB * TT * HH, 256, spat_smem>>>(qkv, xavg);
    // 3) temporal attention -> xavg3 = split3((x1 + x2) * 0.5)
    temporal_attn<<<(BB * HH * NN) / 4, 128, temp_smem>>>(qkv, xavg, xavg3);

    // 4) out = xavg @ W_proj + b_proj
    gemm_mma<true><<<dim3(CC / 128, MROWS / 128), 256, gemm_smem>>>(
        xavg3, wproj3, b_proj, out, K3, CC);
}